// round 15
// baseline (speedup 1.0000x reference)
#include <cuda_runtime.h>
#include <stdint.h>

// ---------------- problem constants ----------------
#define BN 4
#define DD 81
#define KK 2048
#define ND 4

// ---------------- fused GEMM config (fp16 m16n8k16) ----------------
#define MPAD 96
#define NTILE 256
#define KCH 64
#define KSPLIT 4
#define KSEG (KK / KSPLIT)  // 512
#define NSTG (KSEG / KCH)   // 8
#define NSTRIDE 264         // u32 words per kpair row (mod 32 = 8 -> conflict-free)
#define ABYTES 12288        // fp16 frag-packed A stage
#define APB 13824           // A + mu4(1024) + rinv(256) + pad, triple buffered
#define BBYTES (32 * NSTRIDE * 4)   // 33792, double buffered
#define BBASE (3 * APB)             // 41472
#define DYN_SMEM (BBASE + 2 * BBYTES)  // 109056

// ---------------- static device scratch ----------------
__device__ float4   g_mu4[BN * KK];                       // mu rows
__device__ float4   g_s2[BN * KK];                        // sig^2 rows
__device__ float    g_w[BN * KK];                         // pi * prod(sig)
__device__ float    g_rinv[BN * KK];
__device__ uint32_t g_Ah[(size_t)BN * 128 * 6 * 128];     // fp16 frag-packed A (x only)
__device__ float    g_part[(size_t)KSPLIT * BN * MPAD * KK]; // split-K partials
__device__ int      g_sync[32];                           // per-(b,ntile) completion counters

// ---------------- helpers ----------------
typedef unsigned long long ull;
__device__ __forceinline__ float frcp(float v) {
    float r; asm("rcp.approx.ftz.f32 %0, %1;" : "=f"(r) : "f"(v)); return r;
}
__device__ __forceinline__ uint32_t f16x2(float lo, float hi) {
    uint32_t r; asm("cvt.rn.f16x2.f32 %0, %1, %2;" : "=r"(r) : "f"(hi), "f"(lo)); return r;
}
__device__ __forceinline__ ull pack2(float lo, float hi) {
    ull r; asm("mov.b64 %0, {%1, %2};" : "=l"(r) : "f"(lo), "f"(hi)); return r;
}
__device__ __forceinline__ ull splat2(float v) {
    ull r; asm("mov.b64 %0, {%1, %1};" : "=l"(r) : "f"(v)); return r;
}
__device__ __forceinline__ void unpack2(ull v, float& lo, float& hi) {
    asm("mov.b64 {%0, %1}, %2;" : "=f"(lo), "=f"(hi) : "l"(v));
}
__device__ __forceinline__ ull add2(ull a, ull b) {
    ull r; asm("add.rn.f32x2 %0, %1, %2;" : "=l"(r) : "l"(a), "l"(b)); return r;
}
__device__ __forceinline__ ull mul2(ull a, ull b) {
    ull r; asm("mul.rn.f32x2 %0, %1, %2;" : "=l"(r) : "l"(a), "l"(b)); return r;
}
__device__ __forceinline__ ull fma2(ull a, ull b, ull c) {
    ull r; asm("fma.rn.f32x2 %0, %1, %2, %3;" : "=l"(r) : "l"(a), "l"(b), "l"(c)); return r;
}
__device__ __forceinline__ uint32_t smem_u32(const void* p) {
    uint32_t a;
    asm("{ .reg .u64 t; cvta.to.shared.u64 t, %1; cvt.u32.u64 %0, t; }" : "=r"(a) : "l"(p));
    return a;
}
__device__ __forceinline__ void cpasync16(uint32_t dst, const void* src) {
    asm volatile("cp.async.cg.shared.global [%0], [%1], 16;" :: "r"(dst), "l"(src));
}
#define CP_COMMIT() asm volatile("cp.async.commit_group;" ::: "memory")
#define CP_WAIT(n)  asm volatile("cp.async.wait_group %0;" :: "n"(n) : "memory")

__device__ __forceinline__ void mma_f16(float* d, const uint32_t* a, const uint32_t* b) {
    asm volatile(
        "mma.sync.aligned.m16n8k16.row.col.f32.f16.f16.f32 "
        "{%0,%1,%2,%3}, {%4,%5,%6,%7}, {%8,%9}, {%0,%1,%2,%3};"
        : "+f"(d[0]), "+f"(d[1]), "+f"(d[2]), "+f"(d[3])
        : "r"(a[0]), "r"(a[1]), "r"(a[2]), "r"(a[3]), "r"(b[0]), "r"(b[1]));
}

// ---------------- K1: param-pack + A fp16 frag-pack + sync reset ----------------
// grid (32, BN) = 128 blocks (1 wave), 256 threads.
// t<192: A-pack for 4 consecutive kb16 blocks (MLP 16). t in [192,256): param pack
// for k = blk*64 + (t-192). t in [224,256) on block (0,0): counter reset.
__global__ void prep_kernel(const float* __restrict__ x,
                            const float* __restrict__ pi,
                            const float* __restrict__ mu,
                            const float* __restrict__ sig) {
    int blk = blockIdx.x, b = blockIdx.y;
    int t = threadIdx.x;
    if (t < 192) {
        int mfg = t >> 5, lane = t & 31;
        int g = lane >> 2, c = lane & 3;
        int m0 = mfg * 16 + g, m1 = m0 + 8;
        const float* xb = x + (size_t)b * DD * KK;
        float2 z = make_float2(0.0f, 0.0f);
#pragma unroll
        for (int j = 0; j < 4; j++) {
            int kb = blk * 4 + j;
            int k0 = kb * 16 + 2 * c;
            float2 xa = (m0 < DD) ? *(const float2*)(xb + (size_t)m0 * KK + k0)     : z;
            float2 xb2 = (m0 < DD) ? *(const float2*)(xb + (size_t)m0 * KK + k0 + 8) : z;
            float2 xc = (m1 < DD) ? *(const float2*)(xb + (size_t)m1 * KK + k0)     : z;
            float2 xd = (m1 < DD) ? *(const float2*)(xb + (size_t)m1 * KK + k0 + 8) : z;
            uint4 out;
            out.x = f16x2(xa.x, xa.y);
            out.y = f16x2(xc.x, xc.y);
            out.z = f16x2(xb2.x, xb2.y);
            out.w = f16x2(xd.x, xd.y);
            *(uint4*)(g_Ah + (((size_t)(b * 128 + kb) * 6 + mfg) * 128 + lane * 4)) = out;
        }
    } else {
        int k = blk * 64 + (t - 192);
        int i = b * KK + k;
        float mv[4], sv[4], prod = 1.0f;
#pragma unroll
        for (int n = 0; n < ND; n++) {
            mv[n] = mu[(b * ND + n) * KK + k];
            float s = sig[(b * ND + n) * KK + k];
            sv[n] = s * s;
            prod *= s;
        }
        g_mu4[i] = make_float4(mv[0], mv[1], mv[2], mv[3]);
        g_s2[i]  = make_float4(sv[0], sv[1], sv[2], sv[3]);
        g_w[i]   = pi[i] * prod;
        if (t >= 224 && blk == 0 && b == 0)
            g_sync[t - 224] = 0;    // reset split-K completion counters each call
    }
}

// ---------------- K2: row sums (512 blocks, 16 p rows each; 36B/component) ----------------
__global__ __launch_bounds__(256) void rowsum_kernel() {
    int b = blockIdx.y;
    int p0 = blockIdx.x * 16;
    int tid = threadIdx.x;

    __shared__ float smu[16][4];
    if (tid < 16) {
        float4 v = g_mu4[b * KK + p0 + tid];
        smu[tid][0] = v.x; smu[tid][1] = v.y; smu[tid][2] = v.z; smu[tid][3] = v.w;
    }
    __syncthreads();

    ull muPP[8][4];
#pragma unroll
    for (int j = 0; j < 8; j++)
#pragma unroll
        for (int n = 0; n < 4; n++) muPP[j][n] = pack2(smu[2 * j][n], smu[2 * j + 1][n]);

    float acc[16];
#pragma unroll
    for (int j = 0; j < 16; j++) acc[j] = 0.0f;

    for (int m = tid; m < KK; m += 256) {
        float4 cm = g_mu4[b * KK + m];
        float4 cs = g_s2[b * KK + m];
        float w = g_w[b * KK + m];
        ull nm0 = splat2(-cm.x), nm1 = splat2(-cm.y), nm2 = splat2(-cm.z), nm3 = splat2(-cm.w);
        ull s0 = splat2(cs.x), s1 = splat2(cs.y), s2 = splat2(cs.z), s3 = splat2(cs.w);
#pragma unroll
        for (int j = 0; j < 8; j++) {
            ull d0 = add2(muPP[j][0], nm0);
            ull d1 = add2(muPP[j][1], nm1);
            ull d2 = add2(muPP[j][2], nm2);
            ull d3 = add2(muPP[j][3], nm3);
            ull q = mul2(mul2(fma2(d0, d0, s0), fma2(d1, d1, s1)),
                         mul2(fma2(d2, d2, s2), fma2(d3, d3, s3)));
            float ql, qh; unpack2(q, ql, qh);
            acc[2 * j]     = fmaf(w, frcp(ql), acc[2 * j]);
            acc[2 * j + 1] = fmaf(w, frcp(qh), acc[2 * j + 1]);
        }
    }

    __shared__ float red[8][17];
    int lane = tid & 31, wid = tid >> 5;
#pragma unroll
    for (int j = 0; j < 16; j++) {
        float v = acc[j];
#pragma unroll
        for (int o = 16; o > 0; o >>= 1) v += __shfl_xor_sync(0xffffffffu, v, o);
        if (lane == 0) red[wid][j] = v;
    }
    __syncthreads();
    if (tid < 16) {
        float s = 0.0f;
#pragma unroll
        for (int w = 0; w < 8; w++) s += red[w][tid];
        g_rinv[b * KK + p0 + tid] = 1.0f / s;
    }
}

// ---------------- K3: fused fp16 GEMM + last-CTA split-K reduce ----------------
// grid (KK/NTILE=8, KSPLIT=4, BN=4) = 128 CTAs, 512 threads (16 warps = 2M x 8N).
__global__ __launch_bounds__(512, 1) void gemm_fused(float* __restrict__ y) {
    extern __shared__ char dsm[];
    uint32_t sbase = smem_u32(dsm);

    int tid = threadIdx.x, wid = tid >> 5, lane = tid & 31;
    int n0 = blockIdx.x * NTILE, ks = blockIdx.y, b = blockIdx.z;
    int kb0 = ks * (KSEG / 16);

    int ncol = tid & 255;
    int khalf = tid >> 8;
    ull snmu[4], s2v[4];
    float w_m;
    {
        float4 m4 = g_mu4[b * KK + n0 + ncol];
        float4 s4 = g_s2[b * KK + n0 + ncol];
        snmu[0] = splat2(-m4.x); snmu[1] = splat2(-m4.y);
        snmu[2] = splat2(-m4.z); snmu[3] = splat2(-m4.w);
        s2v[0] = splat2(s4.x); s2v[1] = splat2(s4.y);
        s2v[2] = splat2(s4.z); s2v[3] = splat2(s4.w);
        w_m = g_w[b * KK + n0 + ncol];
    }

    int warpM = wid >> 3, warpN = wid & 7;
    int nbase = warpN * 32;
    int g = lane >> 2, c = lane & 3;
    float acc[3][4][4];
#pragma unroll
    for (int i = 0; i < 3; i++)
#pragma unroll
        for (int j = 0; j < 4; j++)
#pragma unroll
            for (int q = 0; q < 4; q++) acc[i][j][q] = 0.0f;

    const uint4* gA = (const uint4*)(g_Ah + (size_t)b * 128 * 6 * 128);
    const float4* gP = &g_mu4[b * KK + ks * KSEG];
    const float* gRi = g_rinv + b * KK + ks * KSEG;

    auto cp_stage = [&](int s) {
        uint32_t ab = sbase + (uint32_t)(s % 3) * APB;
        const uint4* srcA = gA + (size_t)(kb0 + s * 4) * 192;
        cpasync16(ab + (uint32_t)tid * 16u, srcA + tid);
        if (tid < 256) cpasync16(ab + (uint32_t)(tid + 512) * 16u, srcA + tid + 512);
        if (tid < 64) cpasync16(ab + 12288u + (uint32_t)tid * 16u, gP + s * 64 + tid);
        if (tid < 16) cpasync16(ab + 13312u + (uint32_t)tid * 16u, gRi + s * 64 + tid * 4);
        CP_COMMIT();
    };

    auto gen_chunk = [&](int s, int kb) {
        uint32_t* Bs = (uint32_t*)(dsm + BBASE + (size_t)(s & 1) * BBYTES);
        const float* P = (const float*)(dsm + (size_t)(s % 3) * APB + 12288);
        const float* RI = (const float*)(dsm + (size_t)(s % 3) * APB + 13312);
#pragma unroll
        for (int i = 0; i < 4; i++) {
            int kp = kb * 8 + khalf * 4 + i;
            int p2 = kp * 2;
            float4 mp0 = *(const float4*)(P + p2 * 4);
            float4 mp1 = *(const float4*)(P + p2 * 4 + 4);
            float2 ri = *(const float2*)(RI + p2);
            ull d0 = add2(pack2(mp0.x, mp1.x), snmu[0]);
            ull d1 = add2(pack2(mp0.y, mp1.y), snmu[1]);
            ull d2 = add2(pack2(mp0.z, mp1.z), snmu[2]);
            ull d3 = add2(pack2(mp0.w, mp1.w), snmu[3]);
            ull q = mul2(mul2(fma2(d0, d0, s2v[0]), fma2(d1, d1, s2v[1])),
                         mul2(fma2(d2, d2, s2v[2]), fma2(d3, d3, s2v[3])));
            float ql, qh; unpack2(q, ql, qh);
            float v0 = w_m * ri.x * frcp(ql);
            float v1 = w_m * ri.y * frcp(qh);
            Bs[kp * NSTRIDE + ncol] = f16x2(v0, v1);
        }
    };

    auto mma_kb = [&](int s, int kb) {
        const uint4* A4 = (const uint4*)(dsm + (size_t)(s % 3) * APB);
        const uint32_t* B = (const uint32_t*)(dsm + BBASE + (size_t)(s & 1) * BBYTES);
        uint32_t af[3][4], bf[4][2];
#pragma unroll
        for (int mf = 0; mf < 3; mf++) {
            uint4 av = A4[(kb * 6 + warpM * 3 + mf) * 32 + lane];
            af[mf][0] = av.x; af[mf][1] = av.y; af[mf][2] = av.z; af[mf][3] = av.w;
        }
        const uint32_t* Br0 = B + (kb * 8 + c) * NSTRIDE + nbase + g;
        const uint32_t* Br1 = B + (kb * 8 + c + 4) * NSTRIDE + nbase + g;
#pragma unroll
        for (int nf = 0; nf < 4; nf++) {
            bf[nf][0] = Br0[nf * 8];
            bf[nf][1] = Br1[nf * 8];
        }
#pragma unroll
        for (int mf = 0; mf < 3; mf++)
#pragma unroll
            for (int nf = 0; nf < 4; nf++)
                mma_f16(acc[mf][nf], af[mf], bf[nf]);
    };

    cp_stage(0);
    cp_stage(1);
    CP_WAIT(1);
    __syncthreads();
#pragma unroll
    for (int kb = 0; kb < 4; kb++) gen_chunk(0, kb);
    __syncthreads();

    for (int s = 0; s < NSTG; s++) {
        if (s + 2 < NSTG) { cp_stage(s + 2); CP_WAIT(1); }
        else              { CP_WAIT(0); }
        if (s + 1 < NSTG) {
#pragma unroll
            for (int kb = 0; kb < 4; kb++) {
                gen_chunk(s + 1, kb);
                mma_kb(s, kb);
            }
        } else {
#pragma unroll
            for (int kb = 0; kb < 4; kb++) mma_kb(s, kb);
        }
        __syncthreads();
    }

    // ---- write partial tile ----
    float* pp = g_part + ((size_t)(ks * BN + b) * MPAD) * KK + n0;
    int tig = lane & 3;
#pragma unroll
    for (int mf = 0; mf < 3; mf++) {
        int r0 = warpM * 48 + mf * 16 + g;
#pragma unroll
        for (int nf = 0; nf < 4; nf++) {
            int cc = nbase + nf * 8 + tig * 2;
            if (r0 < DD)
                *(float2*)(pp + (size_t)r0 * KK + cc)       = make_float2(acc[mf][nf][0], acc[mf][nf][1]);
            if (r0 + 8 < DD)
                *(float2*)(pp + (size_t)(r0 + 8) * KK + cc) = make_float2(acc[mf][nf][2], acc[mf][nf][3]);
        }
    }

    // ---- last-arriving slice CTA reduces this (b, ntile) tile ----
    __shared__ int s_last;
    __threadfence();                          // release partial writes
    __syncthreads();                          // all threads' STGs issued before tid 0 arrives
    if (tid == 0) {
        int old = atomicAdd(&g_sync[b * 8 + blockIdx.x], 1);
        s_last = (old == KSPLIT - 1) ? 1 : 0;
    }
    __syncthreads();
    if (s_last) {
        __threadfence();                      // acquire other slices' writes
        const size_t slice = (size_t)BN * MPAD * KK;
        float* yb = y + (size_t)b * DD * KK + n0;
        const float* p0b = g_part + ((size_t)b * MPAD) * KK + n0;
        for (int i = tid; i < DD * 64; i += 512) {    // 64 float4 per row
            int d = i >> 6, cq = (i & 63) * 4;
            const float* pr = p0b + (size_t)d * KK + cq;
            float4 v0 = *(const float4*)(pr);
            float4 v1 = *(const float4*)(pr + slice);
            float4 v2 = *(const float4*)(pr + 2 * slice);
            float4 v3 = *(const float4*)(pr + 3 * slice);
            *(float4*)(yb + (size_t)d * KK + cq) =
                make_float4(v0.x + v1.x + v2.x + v3.x,
                            v0.y + v1.y + v2.y + v3.y,
                            v0.z + v1.z + v2.z + v3.z,
                            v0.w + v1.w + v2.w + v3.w);
        }
    }
}

// ---------------- launch ----------------
extern "C" void kernel_launch(void* const* d_in, const int* in_sizes, int n_in,
                              void* d_out, int out_size) {
    const float* x   = (const float*)d_in[0];  // (B, D, K)
    const float* pi  = (const float*)d_in[1];  // (B, 1, K)
    const float* mu  = (const float*)d_in[2];  // (B, ND, K)
    const float* sig = (const float*)d_in[3];  // (B, ND, K)
    float* y = (float*)d_out;                  // (B, D, K)

    cudaFuncSetAttribute(gemm_fused, cudaFuncAttributeMaxDynamicSharedMemorySize, DYN_SMEM);

    prep_kernel<<<dim3(32, BN), 256>>>(x, pi, mu, sig);
    rowsum_kernel<<<dim3(KK / 16, BN), 256>>>();
    gemm_fused<<<dim3(KK / NTILE, KSPLIT, BN), 512, DYN_SMEM>>>(y);
}

// round 16
// speedup vs baseline: 1.0049x; 1.0049x over previous
#include <cuda_runtime.h>
#include <stdint.h>

// ---------------- problem constants ----------------
#define BN 4
#define DD 81
#define KK 2048
#define ND 4

// ---------------- fused GEMM config (fp16 m16n8k16) ----------------
#define MPAD 96
#define NTILE 256
#define KCH 64
#define KSPLIT 4
#define KSEG (KK / KSPLIT)  // 512
#define NSTG (KSEG / KCH)   // 8
#define NSTRIDE 264         // u32 words per kpair row (mod 32 = 8 -> conflict-free)
#define ABYTES 12288        // fp16 frag-packed A stage
#define APB 13824           // A + mu4(1024) + rinv(256) + pad, triple buffered
#define BBYTES (32 * NSTRIDE * 4)   // 33792, double buffered
#define BBASE (3 * APB)             // 41472
#define DYN_SMEM (BBASE + 2 * BBYTES)  // 109056

// ---------------- static device scratch ----------------
__device__ float    g_pp[(size_t)BN * KK * 12];           // {mu[4], sig2[4], w, pad[3]}
__device__ float4   g_mu4[BN * KK];                       // compact mu rows
__device__ float    g_rinv[BN * KK];
__device__ uint32_t g_Ah[(size_t)BN * 128 * 6 * 128];     // fp16 frag-packed A (x only)
__device__ float    g_part[(size_t)KSPLIT * BN * MPAD * KK]; // split-K partials

// ---------------- helpers ----------------
typedef unsigned long long ull;
__device__ __forceinline__ float frcp(float v) {
    float r; asm("rcp.approx.ftz.f32 %0, %1;" : "=f"(r) : "f"(v)); return r;
}
__device__ __forceinline__ uint32_t f16x2(float lo, float hi) {
    uint32_t r; asm("cvt.rn.f16x2.f32 %0, %1, %2;" : "=r"(r) : "f"(hi), "f"(lo)); return r;
}
__device__ __forceinline__ ull pack2(float lo, float hi) {
    ull r; asm("mov.b64 %0, {%1, %2};" : "=l"(r) : "f"(lo), "f"(hi)); return r;
}
__device__ __forceinline__ ull splat2(float v) {
    ull r; asm("mov.b64 %0, {%1, %1};" : "=l"(r) : "f"(v)); return r;
}
__device__ __forceinline__ void unpack2(ull v, float& lo, float& hi) {
    asm("mov.b64 {%0, %1}, %2;" : "=f"(lo), "=f"(hi) : "l"(v));
}
__device__ __forceinline__ ull add2(ull a, ull b) {
    ull r; asm("add.rn.f32x2 %0, %1, %2;" : "=l"(r) : "l"(a), "l"(b)); return r;
}
__device__ __forceinline__ ull mul2(ull a, ull b) {
    ull r; asm("mul.rn.f32x2 %0, %1, %2;" : "=l"(r) : "l"(a), "l"(b)); return r;
}
__device__ __forceinline__ ull fma2(ull a, ull b, ull c) {
    ull r; asm("fma.rn.f32x2 %0, %1, %2, %3;" : "=l"(r) : "l"(a), "l"(b), "l"(c)); return r;
}
__device__ __forceinline__ uint32_t smem_u32(const void* p) {
    uint32_t a;
    asm("{ .reg .u64 t; cvta.to.shared.u64 t, %1; cvt.u32.u64 %0, t; }" : "=r"(a) : "l"(p));
    return a;
}
__device__ __forceinline__ void cpasync16(uint32_t dst, const void* src) {
    asm volatile("cp.async.cg.shared.global [%0], [%1], 16;" :: "r"(dst), "l"(src));
}
#define CP_COMMIT() asm volatile("cp.async.commit_group;" ::: "memory")
#define CP_WAIT(n)  asm volatile("cp.async.wait_group %0;" :: "n"(n) : "memory")

__device__ __forceinline__ void mma_f16(float* d, const uint32_t* a, const uint32_t* b) {
    asm volatile(
        "mma.sync.aligned.m16n8k16.row.col.f32.f16.f16.f32 "
        "{%0,%1,%2,%3}, {%4,%5,%6,%7}, {%8,%9}, {%0,%1,%2,%3};"
        : "+f"(d[0]), "+f"(d[1]), "+f"(d[2]), "+f"(d[3])
        : "r"(a[0]), "r"(a[1]), "r"(a[2]), "r"(a[3]), "r"(b[0]), "r"(b[1]));
}

// ---------------- K1: pack params (R9) ----------------
__global__ void prep_kernel(const float* __restrict__ pi,
                            const float* __restrict__ mu,
                            const float* __restrict__ sig) {
    int i = blockIdx.x * 256 + threadIdx.x;
    if (i >= BN * KK) return;
    int b = i / KK, k = i - b * KK;
    float mv[4], sv[4], prod = 1.0f;
#pragma unroll
    for (int n = 0; n < ND; n++) {
        mv[n] = mu[(b * ND + n) * KK + k];
        float s = sig[(b * ND + n) * KK + k];
        sv[n] = s * s;
        prod *= s;
    }
    float* dst = g_pp + (size_t)i * 12;
    *(float4*)(dst + 0) = make_float4(mv[0], mv[1], mv[2], mv[3]);
    *(float4*)(dst + 4) = make_float4(sv[0], sv[1], sv[2], sv[3]);
    *(float4*)(dst + 8) = make_float4(pi[i] * prod, 0.0f, 0.0f, 0.0f);
    g_mu4[i] = make_float4(mv[0], mv[1], mv[2], mv[3]);
}

// ---------------- K2: row sums (R9: 512 blocks, 16 p rows each) ----------------
__global__ __launch_bounds__(256) void rowsum_kernel() {
    int b = blockIdx.y;
    int p0 = blockIdx.x * 16;
    int tid = threadIdx.x;

    __shared__ float smu[16][4];
    if (tid < 16) {
        float4 v = g_mu4[b * KK + p0 + tid];
        smu[tid][0] = v.x; smu[tid][1] = v.y; smu[tid][2] = v.z; smu[tid][3] = v.w;
    }
    __syncthreads();

    ull muPP[8][4];
#pragma unroll
    for (int j = 0; j < 8; j++)
#pragma unroll
        for (int n = 0; n < 4; n++) muPP[j][n] = pack2(smu[2 * j][n], smu[2 * j + 1][n]);

    float acc[16];
#pragma unroll
    for (int j = 0; j < 16; j++) acc[j] = 0.0f;

    for (int m = tid; m < KK; m += 256) {
        const float* c = g_pp + (size_t)(b * KK + m) * 12;
        float4 cm = *(const float4*)c;
        float4 cs = *(const float4*)(c + 4);
        float w = c[8];
        ull nm0 = splat2(-cm.x), nm1 = splat2(-cm.y), nm2 = splat2(-cm.z), nm3 = splat2(-cm.w);
        ull s0 = splat2(cs.x), s1 = splat2(cs.y), s2 = splat2(cs.z), s3 = splat2(cs.w);
#pragma unroll
        for (int j = 0; j < 8; j++) {
            ull d0 = add2(muPP[j][0], nm0);
            ull d1 = add2(muPP[j][1], nm1);
            ull d2 = add2(muPP[j][2], nm2);
            ull d3 = add2(muPP[j][3], nm3);
            ull q = mul2(mul2(fma2(d0, d0, s0), fma2(d1, d1, s1)),
                         mul2(fma2(d2, d2, s2), fma2(d3, d3, s3)));
            float ql, qh; unpack2(q, ql, qh);
            acc[2 * j]     = fmaf(w, frcp(ql), acc[2 * j]);
            acc[2 * j + 1] = fmaf(w, frcp(qh), acc[2 * j + 1]);
        }
    }

    __shared__ float red[8][17];
    int lane = tid & 31, wid = tid >> 5;
#pragma unroll
    for (int j = 0; j < 16; j++) {
        float v = acc[j];
#pragma unroll
        for (int o = 16; o > 0; o >>= 1) v += __shfl_xor_sync(0xffffffffu, v, o);
        if (lane == 0) red[wid][j] = v;
    }
    __syncthreads();
    if (tid < 16) {
        float s = 0.0f;
#pragma unroll
        for (int w = 0; w < 8; w++) s += red[w][tid];
        g_rinv[b * KK + p0 + tid] = 1.0f / s;
    }
}

// ---------------- K3: A (raw x) -> fp16 m16n8k16 frag-packed layout (R9) ----------------
__global__ void aprep_kernel(const float* __restrict__ x) {
    int kb = blockIdx.x, b = blockIdx.y;
    int t = threadIdx.x;
    int mfg = t >> 5, lane = t & 31;
    int g = lane >> 2, c = lane & 3;
    int m0 = mfg * 16 + g, m1 = m0 + 8;
    int k0 = kb * 16 + 2 * c;

    const float* xb = x + (size_t)b * DD * KK;
    float2 z = make_float2(0.0f, 0.0f);
    float2 xa = (m0 < DD) ? *(const float2*)(xb + (size_t)m0 * KK + k0)     : z;
    float2 xb2 = (m0 < DD) ? *(const float2*)(xb + (size_t)m0 * KK + k0 + 8) : z;
    float2 xc = (m1 < DD) ? *(const float2*)(xb + (size_t)m1 * KK + k0)     : z;
    float2 xd = (m1 < DD) ? *(const float2*)(xb + (size_t)m1 * KK + k0 + 8) : z;

    uint4 out;
    out.x = f16x2(xa.x, xa.y);
    out.y = f16x2(xc.x, xc.y);
    out.z = f16x2(xb2.x, xb2.y);
    out.w = f16x2(xd.x, xd.y);
    *(uint4*)(g_Ah + (((size_t)(b * 128 + kb) * 6 + mfg) * 128 + lane * 4)) = out;
}

// ---------------- K4: fused fp16 GEMM (R9 core; epilogue skips pad rows) ----------------
__global__ __launch_bounds__(512, 1) void gemm_fused() {
    extern __shared__ char dsm[];
    uint32_t sbase = smem_u32(dsm);

    int tid = threadIdx.x, wid = tid >> 5, lane = tid & 31;
    int n0 = blockIdx.x * NTILE, ks = blockIdx.y, b = blockIdx.z;
    int kb0 = ks * (KSEG / 16);

    int ncol = tid & 255;
    int khalf = tid >> 8;
    ull snmu[4], s2v[4];
    float w_m;
    {
        const float* cp = g_pp + (size_t)(b * KK + n0 + ncol) * 12;
#pragma unroll
        for (int n = 0; n < 4; n++) {
            snmu[n] = splat2(-cp[n]);
            s2v[n]  = splat2(cp[4 + n]);
        }
        w_m = cp[8];
    }

    int warpM = wid >> 3, warpN = wid & 7;
    int nbase = warpN * 32;
    int g = lane >> 2, c = lane & 3;
    float acc[3][4][4];
#pragma unroll
    for (int i = 0; i < 3; i++)
#pragma unroll
        for (int j = 0; j < 4; j++)
#pragma unroll
            for (int q = 0; q < 4; q++) acc[i][j][q] = 0.0f;

    const uint4* gA = (const uint4*)(g_Ah + (size_t)b * 128 * 6 * 128);
    const float4* gP = &g_mu4[b * KK + ks * KSEG];
    const float* gRi = g_rinv + b * KK + ks * KSEG;

    auto cp_stage = [&](int s) {
        uint32_t ab = sbase + (uint32_t)(s % 3) * APB;
        const uint4* srcA = gA + (size_t)(kb0 + s * 4) * 192;
        cpasync16(ab + (uint32_t)tid * 16u, srcA + tid);
        if (tid < 256) cpasync16(ab + (uint32_t)(tid + 512) * 16u, srcA + tid + 512);
        if (tid < 64) cpasync16(ab + 12288u + (uint32_t)tid * 16u, gP + s * 64 + tid);
        if (tid < 16) cpasync16(ab + 13312u + (uint32_t)tid * 16u, gRi + s * 64 + tid * 4);
        CP_COMMIT();
    };

    auto gen_chunk = [&](int s, int kb) {
        uint32_t* Bs = (uint32_t*)(dsm + BBASE + (size_t)(s & 1) * BBYTES);
        const float* P = (const float*)(dsm + (size_t)(s % 3) * APB + 12288);
        const float* RI = (const float*)(dsm + (size_t)(s % 3) * APB + 13312);
#pragma unroll
        for (int i = 0; i < 4; i++) {
            int kp = kb * 8 + khalf * 4 + i;
            int p2 = kp * 2;
            float4 mp0 = *(const float4*)(P + p2 * 4);
            float4 mp1 = *(const float4*)(P + p2 * 4 + 4);
            float2 ri = *(const float2*)(RI + p2);
            ull d0 = add2(pack2(mp0.x, mp1.x), snmu[0]);
            ull d1 = add2(pack2(mp0.y, mp1.y), snmu[1]);
            ull d2 = add2(pack2(mp0.z, mp1.z), snmu[2]);
            ull d3 = add2(pack2(mp0.w, mp1.w), snmu[3]);
            ull q = mul2(mul2(fma2(d0, d0, s2v[0]), fma2(d1, d1, s2v[1])),
                         mul2(fma2(d2, d2, s2v[2]), fma2(d3, d3, s2v[3])));
            float ql, qh; unpack2(q, ql, qh);
            float v0 = w_m * ri.x * frcp(ql);
            float v1 = w_m * ri.y * frcp(qh);
            Bs[kp * NSTRIDE + ncol] = f16x2(v0, v1);
        }
    };

    auto mma_kb = [&](int s, int kb) {
        const uint4* A4 = (const uint4*)(dsm + (size_t)(s % 3) * APB);
        const uint32_t* B = (const uint32_t*)(dsm + BBASE + (size_t)(s & 1) * BBYTES);
        uint32_t af[3][4], bf[4][2];
#pragma unroll
        for (int mf = 0; mf < 3; mf++) {
            uint4 av = A4[(kb * 6 + warpM * 3 + mf) * 32 + lane];
            af[mf][0] = av.x; af[mf][1] = av.y; af[mf][2] = av.z; af[mf][3] = av.w;
        }
        const uint32_t* Br0 = B + (kb * 8 + c) * NSTRIDE + nbase + g;
        const uint32_t* Br1 = B + (kb * 8 + c + 4) * NSTRIDE + nbase + g;
#pragma unroll
        for (int nf = 0; nf < 4; nf++) {
            bf[nf][0] = Br0[nf * 8];
            bf[nf][1] = Br1[nf * 8];
        }
#pragma unroll
        for (int mf = 0; mf < 3; mf++)
#pragma unroll
            for (int nf = 0; nf < 4; nf++)
                mma_f16(acc[mf][nf], af[mf], bf[nf]);
    };

    cp_stage(0);
    cp_stage(1);
    CP_WAIT(1);
    __syncthreads();
#pragma unroll
    for (int kb = 0; kb < 4; kb++) gen_chunk(0, kb);
    __syncthreads();

    for (int s = 0; s < NSTG; s++) {
        if (s + 2 < NSTG) { cp_stage(s + 2); CP_WAIT(1); }
        else              { CP_WAIT(0); }
        if (s + 1 < NSTG) {
#pragma unroll
            for (int kb = 0; kb < 4; kb++) {
                gen_chunk(s + 1, kb);
                mma_kb(s, kb);
            }
        } else {
#pragma unroll
            for (int kb = 0; kb < 4; kb++) mma_kb(s, kb);
        }
        __syncthreads();
    }

    float* pp = g_part + ((size_t)(ks * BN + b) * MPAD) * KK + n0;
    int tig = lane & 3;
#pragma unroll
    for (int mf = 0; mf < 3; mf++) {
        int r0 = warpM * 48 + mf * 16 + g;
#pragma unroll
        for (int nf = 0; nf < 4; nf++) {
            int cc = nbase + nf * 8 + tig * 2;
            if (r0 < DD)
                *(float2*)(pp + (size_t)r0 * KK + cc)       = make_float2(acc[mf][nf][0], acc[mf][nf][1]);
            if (r0 + 8 < DD)
                *(float2*)(pp + (size_t)(r0 + 8) * KK + cc) = make_float2(acc[mf][nf][2], acc[mf][nf][3]);
        }
    }
}

// ---------------- K5: split-K reduce, 4 outputs/thread, MLP 16 ----------------
// total float4 = 165888 = 4 * 41472; grid 162 * 256 = 41472 threads exactly.
#define RED_STRIDE 41472
__global__ __launch_bounds__(256) void reduce_kernel(float* __restrict__ y) {
    int t = blockIdx.x * 256 + threadIdx.x;
    const size_t slice = (size_t)BN * MPAD * KK / 4;
    const float4* p = (const float4*)g_part;

    size_t oo[4];
    int ii[4];
#pragma unroll
    for (int u = 0; u < 4; u++) {
        int i = t + u * RED_STRIDE;
        ii[u] = i;
        int e = i * 4;
        int b = e / (DD * KK);
        int r = e - b * (DD * KK);
        int d = r / KK;
        int m = r - d * KK;
        oo[u] = (((size_t)b * MPAD + d) * KK + m) / 4;
    }
    float4 v[4][4];
#pragma unroll
    for (int u = 0; u < 4; u++)
#pragma unroll
        for (int s = 0; s < 4; s++) v[u][s] = __ldcg(&p[oo[u] + s * slice]);
#pragma unroll
    for (int u = 0; u < 4; u++) {
        ((float4*)y)[ii[u]] = make_float4(
            v[u][0].x + v[u][1].x + v[u][2].x + v[u][3].x,
            v[u][0].y + v[u][1].y + v[u][2].y + v[u][3].y,
            v[u][0].z + v[u][1].z + v[u][2].z + v[u][3].z,
            v[u][0].w + v[u][1].w + v[u][2].w + v[u][3].w);
    }
}

// ---------------- launch ----------------
extern "C" void kernel_launch(void* const* d_in, const int* in_sizes, int n_in,
                              void* d_out, int out_size) {
    const float* x   = (const float*)d_in[0];  // (B, D, K)
    const float* pi  = (const float*)d_in[1];  // (B, 1, K)
    const float* mu  = (const float*)d_in[2];  // (B, ND, K)
    const float* sig = (const float*)d_in[3];  // (B, ND, K)
    float* y = (float*)d_out;                  // (B, D, K)

    cudaFuncSetAttribute(gemm_fused, cudaFuncAttributeMaxDynamicSharedMemorySize, DYN_SMEM);

    prep_kernel<<<(BN * KK + 255) / 256, 256>>>(pi, mu, sig);
    rowsum_kernel<<<dim3(KK / 16, BN), 256>>>();
    aprep_kernel<<<dim3(128, BN), 192>>>(x);
    gemm_fused<<<dim3(KK / NTILE, KSPLIT, BN), 512, DYN_SMEM>>>();
    reduce_kernel<<<162, 256>>>(y);
}

// round 17
// speedup vs baseline: 1.1606x; 1.1550x over previous
#include <cuda_runtime.h>
#include <stdint.h>

// ---------------- problem constants ----------------
#define BN 4
#define DD 81
#define KK 2048
#define ND 4

// ---------------- fused GEMM config (fp16 m16n8k16) ----------------
#define MPAD 96
#define NTILE 256
#define KCH 64
#define KSPLIT 4
#define KSEG (KK / KSPLIT)  // 512
#define NSTG (KSEG / KCH)   // 8
#define NSTRIDE 264         // u32 words per kpair row (mod 32 = 8 -> conflict-free)
#define ABYTES 12288        // fp16 frag-packed A stage
#define APB 13824           // A(12288) + P rows(1024) + rinv(256) + pad, triple buffered
#define BBYTES (32 * NSTRIDE * 4)   // 33792, double buffered
#define BBASE (3 * APB)             // 41472
#define DYN_SMEM (BBASE + 2 * BBYTES)  // 109056

// ---------------- static device scratch ----------------
__device__ float    g_rinv[BN * KK];
__device__ uint32_t g_Ah[(size_t)BN * 128 * 6 * 128];     // fp16 frag-packed A (x only)
__device__ float    g_part[(size_t)KSPLIT * BN * MPAD * KK]; // split-K partials

// ---------------- helpers ----------------
typedef unsigned long long ull;
__device__ __forceinline__ float frcp(float v) {
    float r; asm("rcp.approx.ftz.f32 %0, %1;" : "=f"(r) : "f"(v)); return r;
}
__device__ __forceinline__ uint32_t f16x2(float lo, float hi) {
    uint32_t r; asm("cvt.rn.f16x2.f32 %0, %1, %2;" : "=r"(r) : "f"(hi), "f"(lo)); return r;
}
__device__ __forceinline__ ull pack2(float lo, float hi) {
    ull r; asm("mov.b64 %0, {%1, %2};" : "=l"(r) : "f"(lo), "f"(hi)); return r;
}
__device__ __forceinline__ ull splat2(float v) {
    ull r; asm("mov.b64 %0, {%1, %1};" : "=l"(r) : "f"(v)); return r;
}
__device__ __forceinline__ void unpack2(ull v, float& lo, float& hi) {
    asm("mov.b64 {%0, %1}, %2;" : "=f"(lo), "=f"(hi) : "l"(v));
}
__device__ __forceinline__ ull add2(ull a, ull b) {
    ull r; asm("add.rn.f32x2 %0, %1, %2;" : "=l"(r) : "l"(a), "l"(b)); return r;
}
__device__ __forceinline__ ull mul2(ull a, ull b) {
    ull r; asm("mul.rn.f32x2 %0, %1, %2;" : "=l"(r) : "l"(a), "l"(b)); return r;
}
__device__ __forceinline__ ull fma2(ull a, ull b, ull c) {
    ull r; asm("fma.rn.f32x2 %0, %1, %2, %3;" : "=l"(r) : "l"(a), "l"(b), "l"(c)); return r;
}
__device__ __forceinline__ uint32_t smem_u32(const void* p) {
    uint32_t a;
    asm("{ .reg .u64 t; cvta.to.shared.u64 t, %1; cvt.u32.u64 %0, t; }" : "=r"(a) : "l"(p));
    return a;
}
__device__ __forceinline__ void cpasync16(uint32_t dst, const void* src) {
    asm volatile("cp.async.cg.shared.global [%0], [%1], 16;" :: "r"(dst), "l"(src));
}
#define CP_COMMIT() asm volatile("cp.async.commit_group;" ::: "memory")
#define CP_WAIT(n)  asm volatile("cp.async.wait_group %0;" :: "n"(n) : "memory")

__device__ __forceinline__ void mma_f16(float* d, const uint32_t* a, const uint32_t* b) {
    asm volatile(
        "mma.sync.aligned.m16n8k16.row.col.f32.f16.f16.f32 "
        "{%0,%1,%2,%3}, {%4,%5,%6,%7}, {%8,%9}, {%0,%1,%2,%3};"
        : "+f"(d[0]), "+f"(d[1]), "+f"(d[2]), "+f"(d[3])
        : "r"(a[0]), "r"(a[1]), "r"(a[2]), "r"(a[3]), "r"(b[0]), "r"(b[1]));
}

// ---------------- K1: merged rowsum + A-pack (independent roles by blockIdx) ----------------
// blocks [0,512): rowsum for (b = bx>>7, p0 = (bx&127)*16), raw inputs, 256 thr.
// blocks [512,1024): A frag-pack for (kb = (bx-512)&127, b = (bx-512)>>7), t<192 active.
__global__ __launch_bounds__(256) void pre_kernel(const float* __restrict__ x,
                                                  const float* __restrict__ pi,
                                                  const float* __restrict__ mu,
                                                  const float* __restrict__ sig) {
    int bx = blockIdx.x;
    int tid = threadIdx.x;

    if (bx >= 512) {
        // ---- A-pack role ----
        int bx2 = bx - 512;
        int kb = bx2 & 127, b = bx2 >> 7;
        if (tid >= 192) return;
        int mfg = tid >> 5, lane = tid & 31;
        int g = lane >> 2, c = lane & 3;
        int m0 = mfg * 16 + g, m1 = m0 + 8;
        int k0 = kb * 16 + 2 * c;
        const float* xb = x + (size_t)b * DD * KK;
        float2 z = make_float2(0.0f, 0.0f);
        float2 xa = (m0 < DD) ? *(const float2*)(xb + (size_t)m0 * KK + k0)     : z;
        float2 xb2 = (m0 < DD) ? *(const float2*)(xb + (size_t)m0 * KK + k0 + 8) : z;
        float2 xc = (m1 < DD) ? *(const float2*)(xb + (size_t)m1 * KK + k0)     : z;
        float2 xd = (m1 < DD) ? *(const float2*)(xb + (size_t)m1 * KK + k0 + 8) : z;
        uint4 out;
        out.x = f16x2(xa.x, xa.y);
        out.y = f16x2(xc.x, xc.y);
        out.z = f16x2(xb2.x, xb2.y);
        out.w = f16x2(xd.x, xd.y);
        *(uint4*)(g_Ah + (((size_t)(b * 128 + kb) * 6 + mfg) * 128 + lane * 4)) = out;
        return;
    }

    // ---- rowsum role ----
    int b = bx >> 7;
    int p0 = (bx & 127) * 16;

    const float* mu0 = mu + (size_t)(b * ND + 0) * KK;
    const float* mu1 = mu + (size_t)(b * ND + 1) * KK;
    const float* mu2 = mu + (size_t)(b * ND + 2) * KK;
    const float* mu3 = mu + (size_t)(b * ND + 3) * KK;
    const float* sg0 = sig + (size_t)(b * ND + 0) * KK;
    const float* sg1 = sig + (size_t)(b * ND + 1) * KK;
    const float* sg2 = sig + (size_t)(b * ND + 2) * KK;
    const float* sg3 = sig + (size_t)(b * ND + 3) * KK;
    const float* pib = pi + (size_t)b * KK;

    __shared__ float smu[16][4];
    if (tid < 16) {
        smu[tid][0] = mu0[p0 + tid];
        smu[tid][1] = mu1[p0 + tid];
        smu[tid][2] = mu2[p0 + tid];
        smu[tid][3] = mu3[p0 + tid];
    }
    __syncthreads();

    ull muPP[8][4];
#pragma unroll
    for (int j = 0; j < 8; j++)
#pragma unroll
        for (int n = 0; n < 4; n++) muPP[j][n] = pack2(smu[2 * j][n], smu[2 * j + 1][n]);

    float acc[16];
#pragma unroll
    for (int j = 0; j < 16; j++) acc[j] = 0.0f;

    for (int m = tid; m < KK; m += 256) {
        float c0 = mu0[m], c1 = mu1[m], c2 = mu2[m], c3 = mu3[m];
        float t0 = sg0[m], t1 = sg1[m], t2 = sg2[m], t3 = sg3[m];
        float w = pib[m] * ((t0 * t1) * (t2 * t3));
        ull nm0 = splat2(-c0), nm1 = splat2(-c1), nm2 = splat2(-c2), nm3 = splat2(-c3);
        ull s0 = splat2(t0 * t0), s1 = splat2(t1 * t1);
        ull s2 = splat2(t2 * t2), s3 = splat2(t3 * t3);
#pragma unroll
        for (int j = 0; j < 8; j++) {
            ull d0 = add2(muPP[j][0], nm0);
            ull d1 = add2(muPP[j][1], nm1);
            ull d2 = add2(muPP[j][2], nm2);
            ull d3 = add2(muPP[j][3], nm3);
            ull q = mul2(mul2(fma2(d0, d0, s0), fma2(d1, d1, s1)),
                         mul2(fma2(d2, d2, s2), fma2(d3, d3, s3)));
            float ql, qh; unpack2(q, ql, qh);
            acc[2 * j]     = fmaf(w, frcp(ql), acc[2 * j]);
            acc[2 * j + 1] = fmaf(w, frcp(qh), acc[2 * j + 1]);
        }
    }

    __shared__ float red[8][17];
    int lane = tid & 31, wid = tid >> 5;
#pragma unroll
    for (int j = 0; j < 16; j++) {
        float v = acc[j];
#pragma unroll
        for (int o = 16; o > 0; o >>= 1) v += __shfl_xor_sync(0xffffffffu, v, o);
        if (lane == 0) red[wid][j] = v;
    }
    __syncthreads();
    if (tid < 16) {
        float s = 0.0f;
#pragma unroll
        for (int w = 0; w < 8; w++) s += red[w][tid];
        g_rinv[b * KK + p0 + tid] = 1.0f / s;
    }
}

// ---------------- K2: fused fp16 GEMM (params from raw inputs; P staged as 4 rows) ----------------
// grid (KK/NTILE=8, KSPLIT=4, BN=4) = 128 CTAs, 512 threads (16 warps = 2M x 8N).
__global__ __launch_bounds__(512, 1) void gemm_fused(const float* __restrict__ pi,
                                                     const float* __restrict__ mu,
                                                     const float* __restrict__ sig) {
    extern __shared__ char dsm[];
    uint32_t sbase = smem_u32(dsm);

    int tid = threadIdx.x, wid = tid >> 5, lane = tid & 31;
    int n0 = blockIdx.x * NTILE, ks = blockIdx.y, b = blockIdx.z;
    int kb0 = ks * (KSEG / 16);

    int ncol = tid & 255;
    int khalf = tid >> 8;
    ull snmu[4], s2v[4];
    float w_m;
    {
        int idx = n0 + ncol;
        float sgv[4];
        w_m = __ldg(pi + (size_t)b * KK + idx);
#pragma unroll
        for (int n = 0; n < 4; n++) {
            snmu[n] = splat2(-__ldg(mu + (size_t)(b * ND + n) * KK + idx));
            sgv[n] = __ldg(sig + (size_t)(b * ND + n) * KK + idx);
            s2v[n] = splat2(sgv[n] * sgv[n]);
        }
        w_m *= (sgv[0] * sgv[1]) * (sgv[2] * sgv[3]);
    }

    int warpM = wid >> 3, warpN = wid & 7;
    int nbase = warpN * 32;
    int g = lane >> 2, c = lane & 3;
    float acc[3][4][4];
#pragma unroll
    for (int i = 0; i < 3; i++)
#pragma unroll
        for (int j = 0; j < 4; j++)
#pragma unroll
            for (int q = 0; q < 4; q++) acc[i][j][q] = 0.0f;

    const uint4* gA = (const uint4*)(g_Ah + (size_t)b * 128 * 6 * 128);
    const float* gMu = mu + (size_t)b * ND * KK + ks * KSEG;   // rows stride KK
    const float* gRi = g_rinv + b * KK + ks * KSEG;

    auto cp_stage = [&](int s) {
        uint32_t ab = sbase + (uint32_t)(s % 3) * APB;
        const uint4* srcA = gA + (size_t)(kb0 + s * 4) * 192;
        cpasync16(ab + (uint32_t)tid * 16u, srcA + tid);
        if (tid < 256) cpasync16(ab + (uint32_t)(tid + 512) * 16u, srcA + tid + 512);
        if (tid < 64) {
            int row = tid >> 4, c16 = tid & 15;   // 4 mu rows x 16 chunks of 16B
            cpasync16(ab + 12288u + (uint32_t)(row * 256 + c16 * 16),
                      gMu + (size_t)row * KK + s * 64 + c16 * 4);
        }
        if (tid < 16) cpasync16(ab + 13312u + (uint32_t)tid * 16u, gRi + s * 64 + tid * 4);
        CP_COMMIT();
    };

    // gen chunk: this thread's 4 kpairs (8 p) of stage s for kb16 'kb'
    auto gen_chunk = [&](int s, int kb) {
        uint32_t* Bs = (uint32_t*)(dsm + BBASE + (size_t)(s & 1) * BBYTES);
        const float* P = (const float*)(dsm + (size_t)(s % 3) * APB + 12288);  // 4 rows x 64
        const float* RI = (const float*)(dsm + (size_t)(s % 3) * APB + 13312);
#pragma unroll
        for (int i = 0; i < 4; i++) {
            int kp = kb * 8 + khalf * 4 + i;
            int p2 = kp * 2;
            float2 ri = *(const float2*)(RI + p2);
            ull d0 = add2(*(const ull*)(P + p2),       snmu[0]);
            ull d1 = add2(*(const ull*)(P + 64 + p2),  snmu[1]);
            ull d2 = add2(*(const ull*)(P + 128 + p2), snmu[2]);
            ull d3 = add2(*(const ull*)(P + 192 + p2), snmu[3]);
            ull q = mul2(mul2(fma2(d0, d0, s2v[0]), fma2(d1, d1, s2v[1])),
                         mul2(fma2(d2, d2, s2v[2]), fma2(d3, d3, s2v[3])));
            float ql, qh; unpack2(q, ql, qh);
            float v0 = w_m * ri.x * frcp(ql);
            float v1 = w_m * ri.y * frcp(qh);
            Bs[kp * NSTRIDE + ncol] = f16x2(v0, v1);
        }
    };

    auto mma_kb = [&](int s, int kb) {
        const uint4* A4 = (const uint4*)(dsm + (size_t)(s % 3) * APB);
        const uint32_t* B = (const uint32_t*)(dsm + BBASE + (size_t)(s & 1) * BBYTES);
        uint32_t af[3][4], bf[4][2];
#pragma unroll
        for (int mf = 0; mf < 3; mf++) {
            uint4 av = A4[(kb * 6 + warpM * 3 + mf) * 32 + lane];
            af[mf][0] = av.x; af[mf][1] = av.y; af[mf][2] = av.z; af[mf][3] = av.w;
        }
        const uint32_t* Br0 = B + (kb * 8 + c) * NSTRIDE + nbase + g;
        const uint32_t* Br1 = B + (kb * 8 + c + 4) * NSTRIDE + nbase + g;
#pragma unroll
        for (int nf = 0; nf < 4; nf++) {
            bf[nf][0] = Br0[nf * 8];
            bf[nf][1] = Br1[nf * 8];
        }
#pragma unroll
        for (int mf = 0; mf < 3; mf++)
#pragma unroll
            for (int nf = 0; nf < 4; nf++)
                mma_f16(acc[mf][nf], af[mf], bf[nf]);
    };

    cp_stage(0);
    cp_stage(1);
    CP_WAIT(1);
    __syncthreads();
#pragma unroll
    for (int kb = 0; kb < 4; kb++) gen_chunk(0, kb);
    __syncthreads();

    for (int s = 0; s < NSTG; s++) {
        if (s + 2 < NSTG) { cp_stage(s + 2); CP_WAIT(1); }
        else              { CP_WAIT(0); }
        if (s + 1 < NSTG) {
#pragma unroll
            for (int kb = 0; kb < 4; kb++) {
                gen_chunk(s + 1, kb);
                mma_kb(s, kb);
            }
        } else {
#pragma unroll
            for (int kb = 0; kb < 4; kb++) mma_kb(s, kb);
        }
        __syncthreads();
    }

    float* pp = g_part + ((size_t)(ks * BN + b) * MPAD) * KK + n0;
    int tig = lane & 3;
#pragma unroll
    for (int mf = 0; mf < 3; mf++) {
        int r0 = warpM * 48 + mf * 16 + g;
#pragma unroll
        for (int nf = 0; nf < 4; nf++) {
            int cc = nbase + nf * 8 + tig * 2;
            if (r0 < DD)
                *(float2*)(pp + (size_t)r0 * KK + cc)       = make_float2(acc[mf][nf][0], acc[mf][nf][1]);
            if (r0 + 8 < DD)
                *(float2*)(pp + (size_t)(r0 + 8) * KK + cc) = make_float2(acc[mf][nf][2], acc[mf][nf][3]);
        }
    }
}

// ---------------- K3: split-K reduce, 4 outputs/thread, MLP 16 ----------------
// total float4 = 165888 = 4 * 41472; grid 162 * 256 = 41472 threads exactly.
#define RED_STRIDE 41472
__global__ __launch_bounds__(256) void reduce_kernel(float* __restrict__ y) {
    int t = blockIdx.x * 256 + threadIdx.x;
    const size_t slice = (size_t)BN * MPAD * KK / 4;
    const float4* p = (const float4*)g_part;

    size_t oo[4];
    int ii[4];
#pragma unroll
    for (int u = 0; u < 4; u++) {
        int i = t + u * RED_STRIDE;
        ii[u] = i;
        int e = i * 4;
        int b = e / (DD * KK);
        int r = e - b * (DD * KK);
        int d = r / KK;
        int m = r - d * KK;
        oo[u] = (((size_t)b * MPAD + d) * KK + m) / 4;
    }
    float4 v[4][4];
#pragma unroll
    for (int u = 0; u < 4; u++)
#pragma unroll
        for (int s = 0; s < 4; s++) v[u][s] = __ldcg(&p[oo[u] + s * slice]);
#pragma unroll
    for (int u = 0; u < 4; u++) {
        ((float4*)y)[ii[u]] = make_float4(
            v[u][0].x + v[u][1].x + v[u][2].x + v[u][3].x,
            v[u][0].y + v[u][1].y + v[u][2].y + v[u][3].y,
            v[u][0].z + v[u][1].z + v[u][2].z + v[u][3].z,
            v[u][0].w + v[u][1].w + v[u][2].w + v[u][3].w);
    }
}

// ---------------- launch ----------------
extern "C" void kernel_launch(void* const* d_in, const int* in_sizes, int n_in,
                              void* d_out, int out_size) {
    const float* x   = (const float*)d_in[0];  // (B, D, K)
    const float* pi  = (const float*)d_in[1];  // (B, 1, K)
    const float* mu  = (const float*)d_in[2];  // (B, ND, K)
    const float* sig = (const float*)d_in[3];  // (B, ND, K)
    float* y = (float*)d_out;                  // (B, D, K)

    cudaFuncSetAttribute(gemm_fused, cudaFuncAttributeMaxDynamicSharedMemorySize, DYN_SMEM);

    pre_kernel<<<1024, 256>>>(x, pi, mu, sig);
    gemm_fused<<<dim3(KK / NTILE, KSPLIT, BN), 512, DYN_SMEM>>>(pi, mu, sig);
    reduce_kernel<<<162, 256>>>(y);
}